// round 16
// baseline (speedup 1.0000x reference)
#include <cuda_runtime.h>
#include <cstdint>

#define NA_ 8192
#define NN_ 65536
#define NE_ 262144
#define DD_ 128
#define NBLK_ 2
#define GEPS_ 1e-5f

#define ECTA_ 128          // rows (edges/actors/nodes) per CTA
#define XST_  132          // Xst row stride (16B-aligned rows)

using ull = unsigned long long;

// ---- device scratch ----
__device__ float g_A[NA_ * DD_];            // actor state
__device__ float g_agt[NA_ * DD_];          // actors @ Wa^T (+ scatter adds)
__device__ float g_qctx[NA_ * DD_];         // Wc0_mid @ relu(GN(A @ Wq^T))
__device__ float g_nctx[NBLK_][NN_ * DD_];  // Wc0_hi @ nodes, per block
// k-major transposed weights: [blk][tile][k][j], tile order:
// 0 dist1, 1 ctx0_lo, 2 ctx0_mid, 3 ctx0_hi, 4 ctx1, 5 query, 6 agt, 7 lin
__device__ __align__(16) float g_Wt[NBLK_ * 8 * 16384];

// ---- packed f32x2 helpers ----
__device__ __forceinline__ ull ffma2_(ull a, ull b, ull c) {
    ull d;
    asm("fma.rn.f32x2 %0, %1, %2, %3;" : "=l"(d) : "l"(a), "l"(b), "l"(c));
    return d;
}
__device__ __forceinline__ ull pack2_(float x, float y) {
    ull d;
    asm("mov.b64 %0, {%1, %2};" : "=l"(d) : "f"(x), "f"(y));
    return d;
}
__device__ __forceinline__ float2 unpack2_(ull v) {
    float2 f;
    asm("mov.b64 {%0, %1}, %2;" : "=f"(f.x), "=f"(f.y) : "l"(v));
    return f;
}

// ============================================================================
// Packed GEMM, weights via direct LDG (L1-resident): out[e][j] = sum_k X*Wt
// 256 thr; warp owns 16 rows as 8 packed pairs; lane owns cols lane+32c.
// Xst smem [k][e] (pairs via LDS.128 broadcast); Wt k-major read per-kk with
// coalesced LDG.32 (L1 hit after first touch). NO internal barriers except
// the entry sync (publishes caller's Xst writes). No trailing sync: caller
// must __syncthreads() before overwriting Xst.
// ============================================================================
__device__ __forceinline__ void gemm_ldg(const float* __restrict__ Wt,
                                         const float* __restrict__ Xst,
                                         ull (&a2)[8][4]) {
    const int tid = threadIdx.x, lane = tid & 31, warp = tid >> 5;
    const int eb = warp * 16;
#pragma unroll
    for (int p = 0; p < 8; p++)
#pragma unroll
        for (int c = 0; c < 4; c++) a2[p][c] = 0ull;

    __syncthreads();   // caller's Xst writes visible to all warps
#pragma unroll 8
    for (int kk = 0; kk < 128; kk++) {
        const float* xr = &Xst[kk * XST_ + eb];
        uint4 q0 = *(const uint4*)(xr);          // LDS.128 broadcast
        uint4 q1 = *(const uint4*)(xr + 4);
        uint4 q2 = *(const uint4*)(xr + 8);
        uint4 q3 = *(const uint4*)(xr + 12);
        ull xp[8];
        xp[0] = pack2_(__uint_as_float(q0.x), __uint_as_float(q0.y));
        xp[1] = pack2_(__uint_as_float(q0.z), __uint_as_float(q0.w));
        xp[2] = pack2_(__uint_as_float(q1.x), __uint_as_float(q1.y));
        xp[3] = pack2_(__uint_as_float(q1.z), __uint_as_float(q1.w));
        xp[4] = pack2_(__uint_as_float(q2.x), __uint_as_float(q2.y));
        xp[5] = pack2_(__uint_as_float(q2.z), __uint_as_float(q2.w));
        xp[6] = pack2_(__uint_as_float(q3.x), __uint_as_float(q3.y));
        xp[7] = pack2_(__uint_as_float(q3.z), __uint_as_float(q3.w));
        const float* wr = Wt + kk * 128 + lane;
#pragma unroll
        for (int c = 0; c < 4; c++) {
            float w = wr[32 * c];                // coalesced LDG, L1-hit
            ull ww = pack2_(w, w);
#pragma unroll
            for (int p = 0; p < 8; p++)
                a2[p][c] = ffma2_(xp[p], ww, a2[p][c]);
        }
    }
}

// GroupNorm(1 group / 128 ch) + optional relu on packed tile (in place).
__device__ __forceinline__ void gn_pack(ull (&a2)[8][4],
                                        const float* __restrict__ g,
                                        const float* __restrict__ b,
                                        int lane, bool do_relu) {
    float gv[4], bv[4];
#pragma unroll
    for (int c = 0; c < 4; c++) {
        gv[c] = g[lane + 32 * c];
        bv[c] = b[lane + 32 * c];
    }
#pragma unroll
    for (int p = 0; p < 8; p++) {
        float2 v[4];
#pragma unroll
        for (int c = 0; c < 4; c++) v[c] = unpack2_(a2[p][c]);
        float sl = 0.f, ssl = 0.f, sh = 0.f, ssh = 0.f;
#pragma unroll
        for (int c = 0; c < 4; c++) {
            sl += v[c].x; ssl += v[c].x * v[c].x;
            sh += v[c].y; ssh += v[c].y * v[c].y;
        }
#pragma unroll
        for (int o = 16; o > 0; o >>= 1) {
            sl  += __shfl_xor_sync(0xffffffffu, sl, o);
            ssl += __shfl_xor_sync(0xffffffffu, ssl, o);
            sh  += __shfl_xor_sync(0xffffffffu, sh, o);
            ssh += __shfl_xor_sync(0xffffffffu, ssh, o);
        }
        float mul = sl * (1.f / 128.f);
        float muh = sh * (1.f / 128.f);
        float il = rsqrtf(ssl * (1.f / 128.f) - mul * mul + GEPS_);
        float ih = rsqrtf(ssh * (1.f / 128.f) - muh * muh + GEPS_);
#pragma unroll
        for (int c = 0; c < 4; c++) {
            float x = (v[c].x - mul) * il * gv[c] + bv[c];
            float y = (v[c].y - muh) * ih * gv[c] + bv[c];
            if (do_relu) { x = fmaxf(x, 0.f); y = fmaxf(y, 0.f); }
            a2[p][c] = pack2_(x, y);
        }
    }
}

// Write packed tile back to Xst transposed ([col][row-pair] -> STS.64)
__device__ __forceinline__ void store_xt(const ull (&a2)[8][4],
                                         float* __restrict__ Xst,
                                         int lane, int eb) {
#pragma unroll
    for (int p = 0; p < 8; p++)
#pragma unroll
        for (int c = 0; c < 4; c++)
            *(ull*)&Xst[(lane + 32 * c) * XST_ + eb + 2 * p] = a2[p][c];
}

// ============================================================================
// Weight transpose pre-pass: g_Wt[blk][t][k][j] = W_t[j][k]
// ============================================================================
__global__ void k_prep(const float* __restrict__ d1W, const float* __restrict__ c0W,
                       const float* __restrict__ c1W, const float* __restrict__ qW,
                       const float* __restrict__ aW, const float* __restrict__ lW) {
    int idx = blockIdx.x * 256 + threadIdx.x;   // NBLK*8*16384 total
    int blk = idx / (8 * 16384);
    int r = idx % (8 * 16384);
    int t = r / 16384;
    int jk = r % 16384;
    int k = jk >> 7, j = jk & 127;
    float w;
    switch (t) {
        case 0:  w = d1W[blk * 16384 + j * 128 + k];       break;
        case 1:  w = c0W[blk * 49152 + j * 384 + k];       break;
        case 2:  w = c0W[blk * 49152 + j * 384 + 128 + k]; break;
        case 3:  w = c0W[blk * 49152 + j * 384 + 256 + k]; break;
        case 4:  w = c1W[blk * 16384 + j * 128 + k];       break;
        case 5:  w = qW[blk * 16384 + j * 128 + k];        break;
        case 6:  w = aW[blk * 16384 + j * 128 + k];        break;
        default: w = lW[blk * 16384 + j * 128 + k];        break;
    }
    g_Wt[idx] = w;   // idx == ((blk*8+t)*128 + k)*128 + j
}

__device__ __forceinline__ const float* wt_tile(int blk, int t) {
    return g_Wt + (size_t)(blk * 8 + t) * 16384;
}

// ============================================================================
// Fused edge pipeline, 128 edges/CTA, 3 GEMM passes.
// ============================================================================
__global__ void __launch_bounds__(256, 2)
k_edge(const float* __restrict__ actor_ctrs, const float* __restrict__ node_ctrs,
       const int* __restrict__ hi, const int* __restrict__ wi,
       const float* __restrict__ W0, const float* __restrict__ b0,
       const float* __restrict__ g1, const float* __restrict__ b1,
       const float* __restrict__ gc0, const float* __restrict__ bc0,
       int blk) {
    extern __shared__ float sm[];
    float* Xst = sm;                         // [128][XST_]
    __shared__ int   his[ECTA_], wis[ECTA_];
    __shared__ float dxs[ECTA_], dys[ECTA_];
    const float* __restrict__ nctx = g_nctx[blk];

    const int e0 = blockIdx.x * ECTA_;
    const int tid = threadIdx.x, lane = tid & 31, warp = tid >> 5;
    const int eb = warp * 16;

    if (tid < ECTA_) {
        int h = hi[e0 + tid], w = wi[e0 + tid];
        his[tid] = h; wis[tid] = w;
        dxs[tid] = actor_ctrs[2 * h] - node_ctrs[2 * w];
        dys[tid] = actor_ctrs[2 * h + 1] - node_ctrs[2 * w + 1];
    }
    __syncthreads();

    // h = relu(dist0 @ diff + b0)  ->  Xst[k][e]
    for (int idx = tid; idx < ECTA_ * 128; idx += 256) {
        int e = idx & 127, k = idx >> 7;
        float v = fmaf(W0[k * 2], dxs[e], fmaf(W0[k * 2 + 1], dys[e], b0[k]));
        Xst[k * XST_ + e] = fmaxf(v, 0.f);
    }
    // (published by gemm_ldg's entry sync)

    ull a2[8][4];
    // pass 1: d = relu(GN(dist1 @ h))  -> Xst
    gemm_ldg(wt_tile(blk, 0), Xst, a2);
    gn_pack(a2, g1, b1, lane, true);
    __syncthreads();                         // all pass-1 Xst reads done
    store_xt(a2, Xst, lane, eb);

    // pass 2: ctx0_lo GEMM; add per-actor/per-node precomputed terms; GN; relu
    gemm_ldg(wt_tile(blk, 1), Xst, a2);
#pragma unroll
    for (int p = 0; p < 8; p++) {
        int h0 = his[eb + 2 * p] * 128, h1 = his[eb + 2 * p + 1] * 128;
        int w0 = wis[eb + 2 * p] * 128, w1 = wis[eb + 2 * p + 1] * 128;
#pragma unroll
        for (int c = 0; c < 4; c++) {
            int col = lane + 32 * c;
            float2 v = unpack2_(a2[p][c]);
            v.x += g_qctx[h0 + col] + nctx[w0 + col];
            v.y += g_qctx[h1 + col] + nctx[w1 + col];
            a2[p][c] = pack2_(v.x, v.y);
        }
    }
    gn_pack(a2, gc0, bc0, lane, true);
    __syncthreads();                         // all pass-2 Xst reads done
    store_xt(a2, Xst, lane, eb);             // m

    // pass 3: m2 = ctx1 @ m; scatter-add
    gemm_ldg(wt_tile(blk, 4), Xst, a2);
#pragma unroll
    for (int p = 0; p < 8; p++) {
        int h0 = his[eb + 2 * p] * 128, h1 = his[eb + 2 * p + 1] * 128;
#pragma unroll
        for (int c = 0; c < 4; c++) {
            float2 v = unpack2_(a2[p][c]);
            atomicAdd(&g_agt[h0 + lane + 32 * c], v.x);
            atomicAdd(&g_agt[h1 + lane + 32 * c], v.y);
        }
    }
}

// ============================================================================
// Actor pre-pass: agt = A@Wa^T; qn = relu(GN(A@Wq^T)); qctx = Wc0mid@qn
// ============================================================================
__global__ void __launch_bounds__(256, 2)
k_actor_pre(const float* __restrict__ gq, const float* __restrict__ bq, int blk) {
    extern __shared__ float sm[];
    float* Xst = sm;
    const int r0 = blockIdx.x * ECTA_;
    const int tid = threadIdx.x, lane = tid & 31, warp = tid >> 5;
    const int eb = warp * 16;

    for (int idx = tid; idx < ECTA_ * 128; idx += 256) {
        int e = idx & 127, k = idx >> 7;
        Xst[k * XST_ + e] = g_A[(r0 + e) * 128 + k];
    }

    ull a2[8][4];
    // agt = A @ Wa^T
    gemm_ldg(wt_tile(blk, 6), Xst, a2);
#pragma unroll
    for (int p = 0; p < 8; p++) {
        int r = (r0 + eb + 2 * p) * 128;
#pragma unroll
        for (int c = 0; c < 4; c++) {
            float2 v = unpack2_(a2[p][c]);
            g_agt[r + lane + 32 * c] = v.x;
            g_agt[r + 128 + lane + 32 * c] = v.y;
        }
    }
    // qn = relu(GN(A @ Wq^T))  (Xst still holds A; no WAR hazard)
    gemm_ldg(wt_tile(blk, 5), Xst, a2);
    gn_pack(a2, gq, bq, lane, true);
    __syncthreads();   // pass reads done before Xst overwrite
    store_xt(a2, Xst, lane, eb);
    // qctx = qn @ Wc0mid^T
    gemm_ldg(wt_tile(blk, 2), Xst, a2);
#pragma unroll
    for (int p = 0; p < 8; p++) {
        int r = (r0 + eb + 2 * p) * 128;
#pragma unroll
        for (int c = 0; c < 4; c++) {
            float2 v = unpack2_(a2[p][c]);
            g_qctx[r + lane + 32 * c] = v.x;
            g_qctx[r + 128 + lane + 32 * c] = v.y;
        }
    }
}

// ============================================================================
// Node pre-pass: nctx[blk] = nodes @ Wc0hi^T  (512 CTAs)
// ============================================================================
__global__ void __launch_bounds__(256, 2)
k_nctx(const float* __restrict__ nodes, int blk) {
    extern __shared__ float sm[];
    float* Xst = sm;
    const int r0 = blockIdx.x * ECTA_;
    const int tid = threadIdx.x, lane = tid & 31, warp = tid >> 5;
    const int eb = warp * 16;
    float* __restrict__ nctx = g_nctx[blk];

    for (int idx = tid; idx < ECTA_ * 128; idx += 256) {
        int e = idx & 127, k = idx >> 7;
        Xst[k * XST_ + e] = nodes[(size_t)(r0 + e) * 128 + k];
    }

    ull a2[8][4];
    gemm_ldg(wt_tile(blk, 3), Xst, a2);
#pragma unroll
    for (int p = 0; p < 8; p++) {
        int r = (r0 + eb + 2 * p) * 128;
#pragma unroll
        for (int c = 0; c < 4; c++) {
            float2 v = unpack2_(a2[p][c]);
            nctx[r + lane + 32 * c] = v.x;
            nctx[r + 128 + lane + 32 * c] = v.y;
        }
    }
}

// ============================================================================
// Actor post-pass: a = relu(GN(agt)); A = relu(GN(a @ Wl^T) + A)
// ============================================================================
__global__ void __launch_bounds__(256, 2)
k_actor_post(const float* __restrict__ ng, const float* __restrict__ nb,
             const float* __restrict__ lg, const float* __restrict__ lb,
             int blk) {
    extern __shared__ float sm[];
    float* Xst = sm;
    const int r0 = blockIdx.x * ECTA_;
    const int tid = threadIdx.x, lane = tid & 31, warp = tid >> 5;
    const int eb = warp * 16;

    ull a2[8][4];
#pragma unroll
    for (int p = 0; p < 8; p++) {
        int r = (r0 + eb + 2 * p) * 128;
#pragma unroll
        for (int c = 0; c < 4; c++)
            a2[p][c] = pack2_(g_agt[r + lane + 32 * c],
                              g_agt[r + 128 + lane + 32 * c]);
    }
    gn_pack(a2, ng, nb, lane, true);
    store_xt(a2, Xst, lane, eb);

    gemm_ldg(wt_tile(blk, 7), Xst, a2);
    gn_pack(a2, lg, lb, lane, false);
#pragma unroll
    for (int p = 0; p < 8; p++) {
        int r = (r0 + eb + 2 * p) * 128;
#pragma unroll
        for (int c = 0; c < 4; c++) {
            float2 v = unpack2_(a2[p][c]);
            int i0 = r + lane + 32 * c, i1 = i0 + 128;
            g_A[i0] = fmaxf(v.x + g_A[i0], 0.f);
            g_A[i1] = fmaxf(v.y + g_A[i1], 0.f);
        }
    }
}

__global__ void k_copy_in(const float* __restrict__ src) {
    int i = blockIdx.x * 256 + threadIdx.x;
    g_A[i] = src[i];
}
__global__ void k_copy_out(float* __restrict__ dst) {
    int i = blockIdx.x * 256 + threadIdx.x;
    dst[i] = g_A[i];
}

extern "C" void kernel_launch(void* const* d_in, const int* in_sizes, int n_in,
                              void* d_out, int out_size) {
    const float* actors     = (const float*)d_in[0];
    const float* nodes      = (const float*)d_in[1];
    const float* actor_ctrs = (const float*)d_in[2];
    const float* node_ctrs  = (const float*)d_in[3];
    const int*   hi         = (const int*)d_in[4];
    const int*   wi         = (const int*)d_in[5];
    const float* dist0_W = (const float*)d_in[6];
    const float* dist0_b = (const float*)d_in[7];
    const float* dist1_W = (const float*)d_in[8];
    const float* dist1_g = (const float*)d_in[9];
    const float* dist1_b = (const float*)d_in[10];
    const float* query_W = (const float*)d_in[11];
    const float* query_g = (const float*)d_in[12];
    const float* query_b = (const float*)d_in[13];
    const float* ctx0_W  = (const float*)d_in[14];
    const float* ctx0_g  = (const float*)d_in[15];
    const float* ctx0_b  = (const float*)d_in[16];
    const float* ctx1_W  = (const float*)d_in[17];
    const float* agt_W   = (const float*)d_in[18];
    const float* norm_g  = (const float*)d_in[19];
    const float* norm_b  = (const float*)d_in[20];
    const float* lin_W   = (const float*)d_in[21];
    const float* lin_g   = (const float*)d_in[22];
    const float* lin_b   = (const float*)d_in[23];

    // one-time side-stream resources (created on the uncaptured warm-up call)
    static cudaStream_t s1 = nullptr;
    static cudaEvent_t evA = nullptr, ev0 = nullptr, ev1 = nullptr;
    if (s1 == nullptr) {
        cudaStreamCreateWithFlags(&s1, cudaStreamNonBlocking);
        cudaEventCreateWithFlags(&evA, cudaEventDisableTiming);
        cudaEventCreateWithFlags(&ev0, cudaEventDisableTiming);
        cudaEventCreateWithFlags(&ev1, cudaEventDisableTiming);
    }

    const int smB = 128 * XST_ * 4;   // 67,584 B (Xst only)
    cudaFuncSetAttribute(k_edge, cudaFuncAttributeMaxDynamicSharedMemorySize, smB);
    cudaFuncSetAttribute(k_actor_pre, cudaFuncAttributeMaxDynamicSharedMemorySize, smB);
    cudaFuncSetAttribute(k_actor_post, cudaFuncAttributeMaxDynamicSharedMemorySize, smB);
    cudaFuncSetAttribute(k_nctx, cudaFuncAttributeMaxDynamicSharedMemorySize, smB);

    k_copy_in<<<NA_ * DD_ / 256, 256>>>(actors);
    k_prep<<<NBLK_ * 8 * 16384 / 256, 256>>>(dist1_W, ctx0_W, ctx1_W,
                                             query_W, agt_W, lin_W);

    // fork: both nctx blocks on side stream
    cudaEventRecord(evA, 0);
    cudaStreamWaitEvent(s1, evA, 0);
    k_nctx<<<NN_ / ECTA_, 256, smB, s1>>>(nodes, 0);
    cudaEventRecord(ev0, s1);
    k_nctx<<<NN_ / ECTA_, 256, smB, s1>>>(nodes, 1);
    cudaEventRecord(ev1, s1);

    for (int i = 0; i < NBLK_; i++) {
        k_actor_pre<<<NA_ / ECTA_, 256, smB>>>(query_g + i * DD_,
                                               query_b + i * DD_, i);
        cudaStreamWaitEvent(0, (i == 0) ? ev0 : ev1, 0);  // join nctx[i]
        k_edge<<<NE_ / ECTA_, 256, smB>>>(actor_ctrs, node_ctrs, hi, wi,
                                          dist0_W + i * DD_ * 2, dist0_b + i * DD_,
                                          dist1_g + i * DD_, dist1_b + i * DD_,
                                          ctx0_g + i * DD_, ctx0_b + i * DD_, i);
        k_actor_post<<<NA_ / ECTA_, 256, smB>>>(norm_g + i * DD_, norm_b + i * DD_,
                                                lin_g + i * DD_, lin_b + i * DD_, i);
    }
    k_copy_out<<<NA_ * DD_ / 256, 256>>>((float*)d_out);
}

// round 17
// speedup vs baseline: 1.0398x; 1.0398x over previous
#include <cuda_runtime.h>
#include <cstdint>

#define NA_ 8192
#define NN_ 65536
#define NE_ 262144
#define DD_ 128
#define NBLK_ 2
#define GEPS_ 1e-5f

#define ECTA_ 128          // rows (edges/actors/nodes) per CTA
#define XST_  132          // Xst row stride (16B-aligned rows)
#define WP2_  132          // Ws chunk row stride ([kk][col], 16B-aligned)

using ull = unsigned long long;

// ---- device scratch ----
__device__ float g_A[NA_ * DD_];            // actor state after block 0
__device__ float g_agt[NA_ * DD_];          // actors @ Wa^T (+ scatter adds)
__device__ float g_qctx[NA_ * DD_];         // Wc0_mid @ relu(GN(A @ Wq^T))
__device__ float g_nctx[NBLK_][NN_ * DD_];  // Wc0_hi @ nodes, per block
// k-major transposed weights: [blk][tile][k][j], tile order:
// 0 dist1, 1 ctx0_lo, 2 ctx0_mid, 3 ctx0_hi, 4 ctx1, 5 query, 6 agt, 7 lin
__device__ __align__(16) float g_Wt[NBLK_ * 8 * 16384];

// ---- packed f32x2 helpers ----
__device__ __forceinline__ ull ffma2_(ull a, ull b, ull c) {
    ull d;
    asm("fma.rn.f32x2 %0, %1, %2, %3;" : "=l"(d) : "l"(a), "l"(b), "l"(c));
    return d;
}
__device__ __forceinline__ ull pack2_(float x, float y) {
    ull d;
    asm("mov.b64 %0, {%1, %2};" : "=l"(d) : "f"(x), "f"(y));
    return d;
}
__device__ __forceinline__ float2 unpack2_(ull v) {
    float2 f;
    asm("mov.b64 {%0, %1}, %2;" : "=f"(f.x), "=f"(f.y) : "l"(v));
    return f;
}
__device__ __forceinline__ uint32_t smem_u32(const void* p) {
    uint32_t a;
    asm("{ .reg .u64 t; cvta.to.shared.u64 t, %1; cvt.u32.u64 %0, t; }"
        : "=r"(a) : "l"(p));
    return a;
}
__device__ __forceinline__ void cp16(uint32_t dst, const float* src) {
    asm volatile("cp.async.cg.shared.global [%0], [%1], 16;"
                 :: "r"(dst), "l"(src) : "memory");
}

// stream one 32x128 W chunk (k-major, [kk][col] pad-132) via 16B cp.async
__device__ __forceinline__ void load_chunk(uint32_t uWs,
                                           const float* __restrict__ Wt,
                                           int k0) {
    const int tid = threadIdx.x;
#pragma unroll
    for (int t = 0; t < 4; t++) {
        int id = tid + t * 256;
        int kk = id >> 5, cg = (id & 31) * 4;
        cp16(uWs + (uint32_t)(kk * WP2_ + cg) * 4u, Wt + (k0 + kk) * 128 + cg);
    }
    asm volatile("cp.async.commit_group;" ::: "memory");
}

// ============================================================================
// Double-buffered packed GEMM: out[e][j] (+)= sum_k X[e][k]*Wt[k][j]
// One __syncthreads per chunk: wait -> sync -> issue next chunk -> compute.
// CALLER CONTRACT: a __syncthreads() must separate the previous gemm_db /
// any Xst writes from this call; gemm_db's first in-loop sync publishes
// caller Xst writes. No trailing sync.
// ============================================================================
__device__ __forceinline__ void gemm_db(const float* __restrict__ Wt,
                                        const float* __restrict__ Xst,
                                        const float* __restrict__ Ws0,
                                        const float* __restrict__ Ws1,
                                        uint32_t uWs0, uint32_t uWs1,
                                        ull (&a2)[8][4]) {
    const int tid = threadIdx.x, lane = tid & 31, warp = tid >> 5;
    const int eb = warp * 16;
#pragma unroll
    for (int p = 0; p < 8; p++)
#pragma unroll
        for (int c = 0; c < 4; c++) a2[p][c] = 0ull;

    load_chunk(uWs0, Wt, 0);
#pragma unroll 1
    for (int c4 = 0; c4 < 4; c4++) {
        asm volatile("cp.async.wait_group 0;" ::: "memory");
        __syncthreads();   // chunk c4 visible; prior reads of other buf done
        if (c4 < 3) load_chunk((c4 & 1) ? uWs0 : uWs1, Wt, (c4 + 1) * 32);
        const float* cur = (c4 & 1) ? Ws1 : Ws0;
        const int k0 = c4 * 32;
#pragma unroll
        for (int kk = 0; kk < 32; kk++) {
            const float* xr = &Xst[(k0 + kk) * XST_ + eb];
            uint4 q0 = *(const uint4*)(xr);          // LDS.128 broadcast
            uint4 q1 = *(const uint4*)(xr + 4);
            uint4 q2 = *(const uint4*)(xr + 8);
            uint4 q3 = *(const uint4*)(xr + 12);
            ull xp[8];
            xp[0] = pack2_(__uint_as_float(q0.x), __uint_as_float(q0.y));
            xp[1] = pack2_(__uint_as_float(q0.z), __uint_as_float(q0.w));
            xp[2] = pack2_(__uint_as_float(q1.x), __uint_as_float(q1.y));
            xp[3] = pack2_(__uint_as_float(q1.z), __uint_as_float(q1.w));
            xp[4] = pack2_(__uint_as_float(q2.x), __uint_as_float(q2.y));
            xp[5] = pack2_(__uint_as_float(q2.z), __uint_as_float(q2.w));
            xp[6] = pack2_(__uint_as_float(q3.x), __uint_as_float(q3.y));
            xp[7] = pack2_(__uint_as_float(q3.z), __uint_as_float(q3.w));
#pragma unroll
            for (int c = 0; c < 4; c++) {
                float w = cur[kk * WP2_ + lane + 32 * c];  // conflict-free
                ull ww = pack2_(w, w);
#pragma unroll
                for (int p = 0; p < 8; p++)
                    a2[p][c] = ffma2_(xp[p], ww, a2[p][c]);
            }
        }
    }
}

// GroupNorm(1 group / 128 ch) + optional relu on packed tile (in place).
__device__ __forceinline__ void gn_pack(ull (&a2)[8][4],
                                        const float* __restrict__ g,
                                        const float* __restrict__ b,
                                        int lane, bool do_relu) {
    float gv[4], bv[4];
#pragma unroll
    for (int c = 0; c < 4; c++) {
        gv[c] = g[lane + 32 * c];
        bv[c] = b[lane + 32 * c];
    }
#pragma unroll
    for (int p = 0; p < 8; p++) {
        float2 v[4];
#pragma unroll
        for (int c = 0; c < 4; c++) v[c] = unpack2_(a2[p][c]);
        float sl = 0.f, ssl = 0.f, sh = 0.f, ssh = 0.f;
#pragma unroll
        for (int c = 0; c < 4; c++) {
            sl += v[c].x; ssl += v[c].x * v[c].x;
            sh += v[c].y; ssh += v[c].y * v[c].y;
        }
#pragma unroll
        for (int o = 16; o > 0; o >>= 1) {
            sl  += __shfl_xor_sync(0xffffffffu, sl, o);
            ssl += __shfl_xor_sync(0xffffffffu, ssl, o);
            sh  += __shfl_xor_sync(0xffffffffu, sh, o);
            ssh += __shfl_xor_sync(0xffffffffu, ssh, o);
        }
        float mul = sl * (1.f / 128.f);
        float muh = sh * (1.f / 128.f);
        float il = rsqrtf(ssl * (1.f / 128.f) - mul * mul + GEPS_);
        float ih = rsqrtf(ssh * (1.f / 128.f) - muh * muh + GEPS_);
#pragma unroll
        for (int c = 0; c < 4; c++) {
            float x = (v[c].x - mul) * il * gv[c] + bv[c];
            float y = (v[c].y - muh) * ih * gv[c] + bv[c];
            if (do_relu) { x = fmaxf(x, 0.f); y = fmaxf(y, 0.f); }
            a2[p][c] = pack2_(x, y);
        }
    }
}

// Write packed tile back to Xst transposed ([col][row-pair] -> STS.64)
__device__ __forceinline__ void store_xt(const ull (&a2)[8][4],
                                         float* __restrict__ Xst,
                                         int lane, int eb) {
#pragma unroll
    for (int p = 0; p < 8; p++)
#pragma unroll
        for (int c = 0; c < 4; c++)
            *(ull*)&Xst[(lane + 32 * c) * XST_ + eb + 2 * p] = a2[p][c];
}

// ============================================================================
// Weight transpose pre-passes.
// k_prep_hi: ctx0_hi tiles (tile 3) for both blocks — unblocks k_nctx ASAP.
// k_prep_rest: the other 7 tiles.
// ============================================================================
__global__ void k_prep_hi(const float* __restrict__ c0W) {
    int idx = blockIdx.x * 256 + threadIdx.x;   // 2*16384 total
    int blk = idx / 16384;
    int jk = idx % 16384;
    int k = jk >> 7, j = jk & 127;
    g_Wt[((blk * 8 + 3) * 128 + k) * 128 + j] =
        c0W[blk * 49152 + j * 384 + 256 + k];
}

__global__ void k_prep_rest(const float* __restrict__ d1W,
                            const float* __restrict__ c0W,
                            const float* __restrict__ c1W,
                            const float* __restrict__ qW,
                            const float* __restrict__ aW,
                            const float* __restrict__ lW) {
    int idx = blockIdx.x * 256 + threadIdx.x;   // NBLK*7*16384 total
    int blk = idx / (7 * 16384);
    int r = idx % (7 * 16384);
    int ti = r / 16384;
    const int tl[7] = {0, 1, 2, 4, 5, 6, 7};
    int t = tl[ti];
    int jk = r % 16384;
    int k = jk >> 7, j = jk & 127;
    float w;
    switch (t) {
        case 0:  w = d1W[blk * 16384 + j * 128 + k];       break;
        case 1:  w = c0W[blk * 49152 + j * 384 + k];       break;
        case 2:  w = c0W[blk * 49152 + j * 384 + 128 + k]; break;
        case 4:  w = c1W[blk * 16384 + j * 128 + k];       break;
        case 5:  w = qW[blk * 16384 + j * 128 + k];        break;
        case 6:  w = aW[blk * 16384 + j * 128 + k];        break;
        default: w = lW[blk * 16384 + j * 128 + k];        break;
    }
    g_Wt[((blk * 8 + t) * 128 + k) * 128 + j] = w;
}

__device__ __forceinline__ const float* wt_tile(int blk, int t) {
    return g_Wt + (size_t)(blk * 8 + t) * 16384;
}

// ============================================================================
// Fused edge pipeline, 128 edges/CTA, 3 GEMM passes.
// ============================================================================
__global__ void __launch_bounds__(256, 2)
k_edge(const float* __restrict__ actor_ctrs, const float* __restrict__ node_ctrs,
       const int* __restrict__ hi, const int* __restrict__ wi,
       const float* __restrict__ W0, const float* __restrict__ b0,
       const float* __restrict__ g1, const float* __restrict__ b1,
       const float* __restrict__ gc0, const float* __restrict__ bc0,
       int blk) {
    extern __shared__ float sm[];
    float* Xst = sm;                         // [128][XST_]
    float* Ws0 = sm + 128 * XST_;            // [32][WP2_]
    float* Ws1 = Ws0 + 32 * WP2_;
    const uint32_t uWs0 = smem_u32(Ws0), uWs1 = smem_u32(Ws1);
    __shared__ int   his[ECTA_], wis[ECTA_];
    __shared__ float dxs[ECTA_], dys[ECTA_];
    const float* __restrict__ nctx = g_nctx[blk];

    const int e0 = blockIdx.x * ECTA_;
    const int tid = threadIdx.x, lane = tid & 31, warp = tid >> 5;
    const int eb = warp * 16;

    if (tid < ECTA_) {
        int h = hi[e0 + tid], w = wi[e0 + tid];
        his[tid] = h; wis[tid] = w;
        dxs[tid] = actor_ctrs[2 * h] - node_ctrs[2 * w];
        dys[tid] = actor_ctrs[2 * h + 1] - node_ctrs[2 * w + 1];
    }
    __syncthreads();

    // h = relu(dist0 @ diff + b0)  ->  Xst[k][e]
    for (int idx = tid; idx < ECTA_ * 128; idx += 256) {
        int e = idx & 127, k = idx >> 7;
        float v = fmaf(W0[k * 2], dxs[e], fmaf(W0[k * 2 + 1], dys[e], b0[k]));
        Xst[k * XST_ + e] = fmaxf(v, 0.f);
    }
    // (published by gemm_db's first in-loop sync)

    ull a2[8][4];
    // pass 1: d = relu(GN(dist1 @ h))  -> Xst
    gemm_db(wt_tile(blk, 0), Xst, Ws0, Ws1, uWs0, uWs1, a2);
    gn_pack(a2, g1, b1, lane, true);
    __syncthreads();                         // all pass-1 reads done
    store_xt(a2, Xst, lane, eb);

    // pass 2: ctx0_lo GEMM; add per-actor/per-node precomputed terms; GN; relu
    gemm_db(wt_tile(blk, 1), Xst, Ws0, Ws1, uWs0, uWs1, a2);
#pragma unroll
    for (int p = 0; p < 8; p++) {
        int h0 = his[eb + 2 * p] * 128, h1 = his[eb + 2 * p + 1] * 128;
        int w0 = wis[eb + 2 * p] * 128, w1 = wis[eb + 2 * p + 1] * 128;
#pragma unroll
        for (int c = 0; c < 4; c++) {
            int col = lane + 32 * c;
            float2 v = unpack2_(a2[p][c]);
            v.x += g_qctx[h0 + col] + nctx[w0 + col];
            v.y += g_qctx[h1 + col] + nctx[w1 + col];
            a2[p][c] = pack2_(v.x, v.y);
        }
    }
    gn_pack(a2, gc0, bc0, lane, true);
    __syncthreads();                         // all pass-2 reads done
    store_xt(a2, Xst, lane, eb);             // m

    // pass 3: m2 = ctx1 @ m; scatter-add
    gemm_db(wt_tile(blk, 4), Xst, Ws0, Ws1, uWs0, uWs1, a2);
#pragma unroll
    for (int p = 0; p < 8; p++) {
        int h0 = his[eb + 2 * p] * 128, h1 = his[eb + 2 * p + 1] * 128;
#pragma unroll
        for (int c = 0; c < 4; c++) {
            float2 v = unpack2_(a2[p][c]);
            atomicAdd(&g_agt[h0 + lane + 32 * c], v.x);
            atomicAdd(&g_agt[h1 + lane + 32 * c], v.y);
        }
    }
}

// ============================================================================
// Actor pre-pass (initial block only): reads src (= actors input).
// agt = src@Wa^T; qn = relu(GN(src@Wq^T)); qctx = Wc0mid@qn
// ============================================================================
__global__ void __launch_bounds__(256, 2)
k_actor_pre(const float* __restrict__ src,
            const float* __restrict__ gq, const float* __restrict__ bq, int blk) {
    extern __shared__ float sm[];
    float* Xst = sm;
    float* Ws0 = sm + 128 * XST_;
    float* Ws1 = Ws0 + 32 * WP2_;
    const uint32_t uWs0 = smem_u32(Ws0), uWs1 = smem_u32(Ws1);
    const int r0 = blockIdx.x * ECTA_;
    const int tid = threadIdx.x, lane = tid & 31, warp = tid >> 5;
    const int eb = warp * 16;

    for (int idx = tid; idx < ECTA_ * 128; idx += 256) {
        int e = idx & 127, k = idx >> 7;
        Xst[k * XST_ + e] = src[(r0 + e) * 128 + k];
    }

    ull a2[8][4];
    // agt = A @ Wa^T
    gemm_db(wt_tile(blk, 6), Xst, Ws0, Ws1, uWs0, uWs1, a2);
#pragma unroll
    for (int p = 0; p < 8; p++) {
        int r = (r0 + eb + 2 * p) * 128;
#pragma unroll
        for (int c = 0; c < 4; c++) {
            float2 v = unpack2_(a2[p][c]);
            g_agt[r + lane + 32 * c] = v.x;
            g_agt[r + 128 + lane + 32 * c] = v.y;
        }
    }
    __syncthreads();   // Ws WAR before next gemm's preload
    // qn = relu(GN(A @ Wq^T))  (Xst still holds A)
    gemm_db(wt_tile(blk, 5), Xst, Ws0, Ws1, uWs0, uWs1, a2);
    gn_pack(a2, gq, bq, lane, true);
    __syncthreads();   // pass reads done before Xst overwrite
    store_xt(a2, Xst, lane, eb);
    // qctx = qn @ Wc0mid^T
    gemm_db(wt_tile(blk, 2), Xst, Ws0, Ws1, uWs0, uWs1, a2);
#pragma unroll
    for (int p = 0; p < 8; p++) {
        int r = (r0 + eb + 2 * p) * 128;
#pragma unroll
        for (int c = 0; c < 4; c++) {
            float2 v = unpack2_(a2[p][c]);
            g_qctx[r + lane + 32 * c] = v.x;
            g_qctx[r + 128 + lane + 32 * c] = v.y;
        }
    }
}

// ============================================================================
// Node pre-pass: nctx[blk] = nodes @ Wc0hi^T  (512 CTAs)
// ============================================================================
__global__ void __launch_bounds__(256, 2)
k_nctx(const float* __restrict__ nodes, int blk) {
    extern __shared__ float sm[];
    float* Xst = sm;
    float* Ws0 = sm + 128 * XST_;
    float* Ws1 = Ws0 + 32 * WP2_;
    const uint32_t uWs0 = smem_u32(Ws0), uWs1 = smem_u32(Ws1);
    const int r0 = blockIdx.x * ECTA_;
    const int tid = threadIdx.x, lane = tid & 31, warp = tid >> 5;
    const int eb = warp * 16;
    float* __restrict__ nctx = g_nctx[blk];

    for (int idx = tid; idx < ECTA_ * 128; idx += 256) {
        int e = idx & 127, k = idx >> 7;
        Xst[k * XST_ + e] = nodes[(size_t)(r0 + e) * 128 + k];
    }

    ull a2[8][4];
    gemm_db(wt_tile(blk, 3), Xst, Ws0, Ws1, uWs0, uWs1, a2);
#pragma unroll
    for (int p = 0; p < 8; p++) {
        int r = (r0 + eb + 2 * p) * 128;
#pragma unroll
        for (int c = 0; c < 4; c++) {
            float2 v = unpack2_(a2[p][c]);
            nctx[r + lane + 32 * c] = v.x;
            nctx[r + 128 + lane + 32 * c] = v.y;
        }
    }
}

// ============================================================================
// Fused actor post(blk) + pre(blk+1):
//   a = relu(GN(agt)); A_new = relu(GN(a@Wl^T) + res)
//   -> write A_new to g_A (blk=0) or outp (blk=1)
//   if do_pre: agt = A_new@Wa^T; qn = relu(GN(A_new@Wq^T)); qctx = Wc0mid@qn
//   (same rows — A_new tile reused directly from registers)
// ============================================================================
__global__ void __launch_bounds__(256, 2)
k_post_pre(const float* __restrict__ ng, const float* __restrict__ nb,
           const float* __restrict__ lg, const float* __restrict__ lb,
           const float* __restrict__ gq, const float* __restrict__ bq,
           const float* __restrict__ res0, float* __restrict__ outp,
           int blk, int do_pre) {
    extern __shared__ float sm[];
    float* Xst = sm;
    float* Ws0 = sm + 128 * XST_;
    float* Ws1 = Ws0 + 32 * WP2_;
    const uint32_t uWs0 = smem_u32(Ws0), uWs1 = smem_u32(Ws1);
    const int r0 = blockIdx.x * ECTA_;
    const int tid = threadIdx.x, lane = tid & 31, warp = tid >> 5;
    const int eb = warp * 16;
    const float* __restrict__ res = (blk == 0) ? res0 : g_A;
    float* __restrict__ dst = (blk == 0) ? g_A : outp;

    ull a2[8][4];
#pragma unroll
    for (int p = 0; p < 8; p++) {
        int r = (r0 + eb + 2 * p) * 128;
#pragma unroll
        for (int c = 0; c < 4; c++)
            a2[p][c] = pack2_(g_agt[r + lane + 32 * c],
                              g_agt[r + 128 + lane + 32 * c]);
    }
    gn_pack(a2, ng, nb, lane, true);
    store_xt(a2, Xst, lane, eb);   // first Xst write; published by gemm entry sync

    gemm_db(wt_tile(blk, 7), Xst, Ws0, Ws1, uWs0, uWs1, a2);   // lin
    gn_pack(a2, lg, lb, lane, false);
#pragma unroll
    for (int p = 0; p < 8; p++) {
        int r = (r0 + eb + 2 * p) * 128;
#pragma unroll
        for (int c = 0; c < 4; c++) {
            int i0 = r + lane + 32 * c, i1 = i0 + 128;
            float2 v = unpack2_(a2[p][c]);
            v.x = fmaxf(v.x + res[i0], 0.f);
            v.y = fmaxf(v.y + res[i1], 0.f);
            dst[i0] = v.x;
            dst[i1] = v.y;
            a2[p][c] = pack2_(v.x, v.y);     // keep A_new in registers
        }
    }
    if (!do_pre) return;

    const int nblk = blk + 1;
    __syncthreads();               // lin-gemm Xst/Ws reads done
    store_xt(a2, Xst, lane, eb);   // A_new -> Xst

    // agt = A_new @ Wa^T
    gemm_db(wt_tile(nblk, 6), Xst, Ws0, Ws1, uWs0, uWs1, a2);
#pragma unroll
    for (int p = 0; p < 8; p++) {
        int r = (r0 + eb + 2 * p) * 128;
#pragma unroll
        for (int c = 0; c < 4; c++) {
            float2 v = unpack2_(a2[p][c]);
            g_agt[r + lane + 32 * c] = v.x;
            g_agt[r + 128 + lane + 32 * c] = v.y;
        }
    }
    __syncthreads();   // Ws WAR before next gemm's preload
    // qn = relu(GN(A_new @ Wq^T))
    gemm_db(wt_tile(nblk, 5), Xst, Ws0, Ws1, uWs0, uWs1, a2);
    gn_pack(a2, gq, bq, lane, true);
    __syncthreads();
    store_xt(a2, Xst, lane, eb);
    // qctx = qn @ Wc0mid^T
    gemm_db(wt_tile(nblk, 2), Xst, Ws0, Ws1, uWs0, uWs1, a2);
#pragma unroll
    for (int p = 0; p < 8; p++) {
        int r = (r0 + eb + 2 * p) * 128;
#pragma unroll
        for (int c = 0; c < 4; c++) {
            float2 v = unpack2_(a2[p][c]);
            g_qctx[r + lane + 32 * c] = v.x;
            g_qctx[r + 128 + lane + 32 * c] = v.y;
        }
    }
}

extern "C" void kernel_launch(void* const* d_in, const int* in_sizes, int n_in,
                              void* d_out, int out_size) {
    const float* actors     = (const float*)d_in[0];
    const float* nodes      = (const float*)d_in[1];
    const float* actor_ctrs = (const float*)d_in[2];
    const float* node_ctrs  = (const float*)d_in[3];
    const int*   hi         = (const int*)d_in[4];
    const int*   wi         = (const int*)d_in[5];
    const float* dist0_W = (const float*)d_in[6];
    const float* dist0_b = (const float*)d_in[7];
    const float* dist1_W = (const float*)d_in[8];
    const float* dist1_g = (const float*)d_in[9];
    const float* dist1_b = (const float*)d_in[10];
    const float* query_W = (const float*)d_in[11];
    const float* query_g = (const float*)d_in[12];
    const float* query_b = (const float*)d_in[13];
    const float* ctx0_W  = (const float*)d_in[14];
    const float* ctx0_g  = (const float*)d_in[15];
    const float* ctx0_b  = (const float*)d_in[16];
    const float* ctx1_W  = (const float*)d_in[17];
    const float* agt_W   = (const float*)d_in[18];
    const float* norm_g  = (const float*)d_in[19];
    const float* norm_b  = (const float*)d_in[20];
    const float* lin_W   = (const float*)d_in[21];
    const float* lin_g   = (const float*)d_in[22];
    const float* lin_b   = (const float*)d_in[23];

    // one-time side-stream resources (created on the uncaptured warm-up call)
    static cudaStream_t s1 = nullptr;
    static cudaEvent_t evA = nullptr, ev0 = nullptr, ev1 = nullptr;
    if (s1 == nullptr) {
        cudaStreamCreateWithFlags(&s1, cudaStreamNonBlocking);
        cudaEventCreateWithFlags(&evA, cudaEventDisableTiming);
        cudaEventCreateWithFlags(&ev0, cudaEventDisableTiming);
        cudaEventCreateWithFlags(&ev1, cudaEventDisableTiming);
    }

    const int smB = (128 * XST_ + 2 * 32 * WP2_) * 4;  // 101,376 B
    cudaFuncSetAttribute(k_edge, cudaFuncAttributeMaxDynamicSharedMemorySize, smB);
    cudaFuncSetAttribute(k_actor_pre, cudaFuncAttributeMaxDynamicSharedMemorySize, smB);
    cudaFuncSetAttribute(k_post_pre, cudaFuncAttributeMaxDynamicSharedMemorySize, smB);
    cudaFuncSetAttribute(k_nctx, cudaFuncAttributeMaxDynamicSharedMemorySize, smB);

    // nctx weights first, then fork nctx onto the side stream immediately
    k_prep_hi<<<NBLK_ * 16384 / 256, 256>>>(ctx0_W);
    cudaEventRecord(evA, 0);
    cudaStreamWaitEvent(s1, evA, 0);
    k_nctx<<<NN_ / ECTA_, 256, smB, s1>>>(nodes, 0);
    cudaEventRecord(ev0, s1);
    k_nctx<<<NN_ / ECTA_, 256, smB, s1>>>(nodes, 1);
    cudaEventRecord(ev1, s1);

    k_prep_rest<<<NBLK_ * 7 * 16384 / 256, 256>>>(dist1_W, ctx0_W, ctx1_W,
                                                  query_W, agt_W, lin_W);
    // block 0
    k_actor_pre<<<NA_ / ECTA_, 256, smB>>>(actors, query_g, query_b, 0);
    cudaStreamWaitEvent(0, ev0, 0);
    k_edge<<<NE_ / ECTA_, 256, smB>>>(actor_ctrs, node_ctrs, hi, wi,
                                      dist0_W, dist0_b,
                                      dist1_g, dist1_b,
                                      ctx0_g, ctx0_b, 0);
    // post(0) fused with pre(1)
    k_post_pre<<<NA_ / ECTA_, 256, smB>>>(norm_g, norm_b, lin_g, lin_b,
                                          query_g + DD_, query_b + DD_,
                                          actors, nullptr, 0, 1);
    // block 1
    cudaStreamWaitEvent(0, ev1, 0);
    k_edge<<<NE_ / ECTA_, 256, smB>>>(actor_ctrs, node_ctrs, hi, wi,
                                      dist0_W + DD_ * 2, dist0_b + DD_,
                                      dist1_g + DD_, dist1_b + DD_,
                                      ctx0_g + DD_, ctx0_b + DD_, 1);
    // post(1): writes final result straight to d_out
    k_post_pre<<<NA_ / ECTA_, 256, smB>>>(norm_g + DD_, norm_b + DD_,
                                          lin_g + DD_, lin_b + DD_,
                                          query_g, query_b,
                                          actors, (float*)d_out, 1, 0);
}